// round 1
// baseline (speedup 1.0000x reference)
#include <cuda_runtime.h>

#define NB   8
#define IMG  256
#define HW   (IMG*IMG)
#define NPIX (NB*HW)
#define BN_N 524288.0   /* 8*256*256 */

// ---------------- static scratch (no allocations allowed) ----------------
__device__ float  g_bufA[NB*128*HW];   // holds 16 / 64 / 128-ch activations
__device__ float  g_bufB[NB*64*HW];    // holds 32 / 64-ch activations
__device__ float  g_maskA[NPIX];
__device__ float  g_maskB[NPIX];
__device__ double g_sum[5*128];
__device__ double g_sq[5*128];
__device__ float  g_scale[5*128];
__device__ float  g_shift[5*128];

// ---------------- zero BN stats each run (graph replays must re-zero) ----
__global__ void zero_stats_k() {
    int i = blockIdx.x*256 + threadIdx.x;
    if (i < 5*128) { g_sum[i] = 0.0; g_sq[i] = 0.0; }
}

// ---------------- fused sparse-conv block -------------------------------
// Computes: y = conv3x3_dil(act(prev)*mask) / max(CIN*boxsum(mask),1e-5) + b
//           m_out = maxpool3x3_dil(mask)
//           accumulates per-channel sum/sumsq of y (for BatchNorm)
// act() = leaky(scale*x + shift) folded from the PREVIOUS block's BN (ACT=true)
template<int CIN, int COUT, int CO_CHUNK, int D, bool ACT>
__global__ void __launch_bounds__(256) conv_block_k(
    const float* __restrict__ x,  const float* __restrict__ m_in,
    const float* __restrict__ W,  const float* __restrict__ bias,
    const float* __restrict__ scale, const float* __restrict__ shift,
    float* __restrict__ y, float* __restrict__ m_out,
    double* __restrict__ s_sum, double* __restrict__ s_sq)
{
    constexpr int TILE = 16;
    constexpr int TW   = TILE + 2*D;
    constexpr int ET   = TW*TW;
    constexpr int CI   = 8;                 // input-channel chunk in smem
    constexpr int CHUNKS = COUT / CO_CHUNK;

    __shared__ float xs[CI*ET];
    __shared__ float ms[ET];
    __shared__ __align__(16) float wsh[CI*9*CO_CHUNK];
    __shared__ float sred[CO_CHUNK][8];
    __shared__ float qred[CO_CHUNK][8];

    const int tid = threadIdx.x;
    const int n   = blockIdx.z / CHUNKS;
    const int cc  = blockIdx.z % CHUNKS;
    const int co0 = cc * CO_CHUNK;
    const int y0  = blockIdx.y*TILE - D;
    const int x0  = blockIdx.x*TILE - D;
    const int ty  = tid >> 4;
    const int tx  = tid & 15;

    // mask tile (zero-padded)
    for (int e = tid; e < ET; e += 256) {
        int iy = e / TW, ix = e % TW;
        int gy = y0 + iy, gx = x0 + ix;
        float mv = 0.f;
        if (gy >= 0 && gy < IMG && gx >= 0 && gx < IMG)
            mv = m_in[n*HW + gy*IMG + gx];
        ms[e] = mv;
    }

    float acc[CO_CHUNK];
#pragma unroll
    for (int c = 0; c < CO_CHUNK; ++c) acc[c] = 0.f;

    for (int cb = 0; cb < CIN/CI; ++cb) {
        __syncthreads();   // covers mask-tile availability (cb=0) and xs reuse
        // stage act(x)*mask for CI channels
        for (int e = tid; e < CI*ET; e += 256) {
            int ci = e / ET, r = e % ET;
            int iy = r / TW, ix = r % TW;
            int gy = y0 + iy, gx = x0 + ix;
            float v = 0.f;
            if (gy >= 0 && gy < IMG && gx >= 0 && gx < IMG) {
                float mv = ms[r];
                if (mv != 0.f) {
                    float raw = x[(size_t)(n*CIN + cb*CI + ci)*HW + gy*IMG + gx];
                    if (ACT) {
                        raw = scale[cb*CI + ci]*raw + shift[cb*CI + ci];
                        raw = raw >= 0.f ? raw : 0.01f*raw;
                    }
                    v = raw * mv;
                }
            }
            xs[e] = v;
        }
        // stage weights as [ci][tap][co] for float4 broadcast
        for (int e = tid; e < CI*9*CO_CHUNK; e += 256) {
            int co  = e % CO_CHUNK;
            int tap = (e / CO_CHUNK) % 9;
            int ci  = e / (9*CO_CHUNK);
            wsh[e] = W[(size_t)(co0 + co)*CIN*9 + (cb*CI + ci)*9 + tap];
        }
        __syncthreads();

#pragma unroll
        for (int ci = 0; ci < CI; ++ci) {
            float xv[9];
#pragma unroll
            for (int kh = 0; kh < 3; ++kh)
#pragma unroll
                for (int kw = 0; kw < 3; ++kw)
                    xv[kh*3+kw] = xs[ci*ET + (ty + kh*D)*TW + tx + kw*D];
#pragma unroll
            for (int tap = 0; tap < 9; ++tap) {
                const float4* wp = (const float4*)&wsh[(ci*9 + tap)*CO_CHUNK];
#pragma unroll
                for (int c4 = 0; c4 < CO_CHUNK/4; ++c4) {
                    float4 w = wp[c4];
                    acc[c4*4+0] += xv[tap]*w.x;
                    acc[c4*4+1] += xv[tap]*w.y;
                    acc[c4*4+2] += xv[tap]*w.z;
                    acc[c4*4+3] += xv[tap]*w.w;
                }
            }
        }
    }

    // mask boxsum / maxpool for this output pixel
    float msum = 0.f, mmax = 0.f;
#pragma unroll
    for (int kh = 0; kh < 3; ++kh)
#pragma unroll
        for (int kw = 0; kw < 3; ++kw) {
            float mv = ms[(ty + kh*D)*TW + tx + kw*D];
            msum += mv;
            mmax = fmaxf(mmax, mv);
        }
    float inv = 1.f / fmaxf((float)CIN * msum, 1e-5f);

    const int gy  = blockIdx.y*TILE + ty;
    const int gx  = blockIdx.x*TILE + tx;
    const int pix = gy*IMG + gx;
    if (cc == 0) m_out[n*HW + pix] = mmax;

    const int lane = tid & 31, w5 = tid >> 5;
#pragma unroll
    for (int c = 0; c < CO_CHUNK; ++c) {
        float v = acc[c]*inv + bias[co0 + c];
        y[(size_t)(n*COUT + co0 + c)*HW + pix] = v;
        float s = v, q = v*v;
#pragma unroll
        for (int o = 16; o > 0; o >>= 1) {
            s += __shfl_xor_sync(0xffffffffu, s, o);
            q += __shfl_xor_sync(0xffffffffu, q, o);
        }
        if (lane == 0) { sred[c][w5] = s; qred[c][w5] = q; }
    }
    __syncthreads();
    if (tid < CO_CHUNK) {
        float s = 0.f, q = 0.f;
#pragma unroll
        for (int w = 0; w < 8; ++w) { s += sred[tid][w]; q += qred[tid][w]; }
        atomicAdd(&s_sum[co0 + tid], (double)s);
        atomicAdd(&s_sq [co0 + tid], (double)q);
    }
}

// ---------------- BN fold: scale/shift per channel ------------------------
__global__ void finalize_k(const double* __restrict__ s_sum,
                           const double* __restrict__ s_sq,
                           const float* __restrict__ g,
                           const float* __restrict__ be,
                           float* __restrict__ scale,
                           float* __restrict__ shift, int C)
{
    int c = threadIdx.x;
    if (c < C) {
        double mean = s_sum[c] / BN_N;
        double var  = s_sq[c] / BN_N - mean*mean;
        float  sc   = g[c] * rsqrtf((float)(var + 1e-5));
        scale[c] = sc;
        shift[c] = be[c] - (float)mean * sc;
    }
}

// ---------------- final 1x1 conv (128 -> 64) with act fold ----------------
__global__ void __launch_bounds__(256) final_conv_k(
    const float* __restrict__ x, const float* __restrict__ scale,
    const float* __restrict__ shift, const float* __restrict__ Wf,
    const float* __restrict__ bf, float* __restrict__ out)
{
    __shared__ __align__(16) float wsh[128*64];
    const int tid = threadIdx.x;
    for (int e = tid; e < 128*64; e += 256) {
        int ci = e >> 6, p = e & 63;
        wsh[e] = Wf[p*128 + ci];
    }
    __syncthreads();

    int gid = blockIdx.x*256 + tid;          // 0 .. 524287
    int n   = gid >> 16;
    int pix = gid & (HW - 1);

    float acc[64];
#pragma unroll
    for (int p = 0; p < 64; ++p) acc[p] = 0.f;

    for (int ci = 0; ci < 128; ++ci) {
        float v = x[((size_t)(n*128 + ci) << 16) + pix];
        v = scale[ci]*v + shift[ci];
        v = v >= 0.f ? v : 0.01f*v;
        const float4* wp = (const float4*)&wsh[ci*64];
#pragma unroll
        for (int c4 = 0; c4 < 16; ++c4) {
            float4 w = wp[c4];
            acc[c4*4+0] += v*w.x;
            acc[c4*4+1] += v*w.y;
            acc[c4*4+2] += v*w.z;
            acc[c4*4+3] += v*w.w;
        }
    }
#pragma unroll
    for (int p = 0; p < 64; ++p)
        out[((size_t)(n*64 + p) << 16) + pix] = acc[p] + bf[p];
}

__global__ void copy_mask_k(const float* __restrict__ m, float* __restrict__ out) {
    int i = blockIdx.x*256 + threadIdx.x;
    if (i < NPIX) out[i] = m[i];
}

// ---------------- launcher ------------------------------------------------
extern "C" void kernel_launch(void* const* d_in, const int* in_sizes, int n_in,
                              void* d_out, int out_size)
{
    (void)in_sizes; (void)n_in; (void)out_size;
    const float* feat = (const float*)d_in[0];
    const float* mask = (const float*)d_in[1];
    const float* Wl[5]; const float* bl[5]; const float* gl[5]; const float* bel[5];
    for (int l = 0; l < 5; ++l) {
        Wl[l]  = (const float*)d_in[2 + 4*l];
        bl[l]  = (const float*)d_in[3 + 4*l];
        gl[l]  = (const float*)d_in[4 + 4*l];
        bel[l] = (const float*)d_in[5 + 4*l];
    }
    const float* Wf = (const float*)d_in[22];
    const float* bf = (const float*)d_in[23];
    float* out = (float*)d_out;

    float *pA, *pB, *pMA, *pMB, *pScale, *pShift;
    double *pSum, *pSq;
    cudaGetSymbolAddress((void**)&pA,     g_bufA);
    cudaGetSymbolAddress((void**)&pB,     g_bufB);
    cudaGetSymbolAddress((void**)&pMA,    g_maskA);
    cudaGetSymbolAddress((void**)&pMB,    g_maskB);
    cudaGetSymbolAddress((void**)&pSum,   g_sum);
    cudaGetSymbolAddress((void**)&pSq,    g_sq);
    cudaGetSymbolAddress((void**)&pScale, g_scale);
    cudaGetSymbolAddress((void**)&pShift, g_shift);

    zero_stats_k<<<3, 256>>>();

    dim3 blk(256);
    // L0: 32 -> 16, d=1, input feat/mask, no act fold
    conv_block_k<32,16,16,1,false><<<dim3(16,16, NB*1), blk>>>(
        feat, mask, Wl[0], bl[0], nullptr, nullptr,
        pA, pMA, pSum + 0*128, pSq + 0*128);
    finalize_k<<<1,128>>>(pSum+0*128, pSq+0*128, gl[0], bel[0], pScale+0*128, pShift+0*128, 16);

    // L1: 16 -> 32, d=2
    conv_block_k<16,32,32,2,true><<<dim3(16,16, NB*1), blk>>>(
        pA, pMA, Wl[1], bl[1], pScale+0*128, pShift+0*128,
        pB, pMB, pSum + 1*128, pSq + 1*128);
    finalize_k<<<1,128>>>(pSum+1*128, pSq+1*128, gl[1], bel[1], pScale+1*128, pShift+1*128, 32);

    // L2: 32 -> 64, d=1
    conv_block_k<32,64,32,1,true><<<dim3(16,16, NB*2), blk>>>(
        pB, pMB, Wl[2], bl[2], pScale+1*128, pShift+1*128,
        pA, pMA, pSum + 2*128, pSq + 2*128);
    finalize_k<<<1,128>>>(pSum+2*128, pSq+2*128, gl[2], bel[2], pScale+2*128, pShift+2*128, 64);

    // L3: 64 -> 64, d=2
    conv_block_k<64,64,32,2,true><<<dim3(16,16, NB*2), blk>>>(
        pA, pMA, Wl[3], bl[3], pScale+2*128, pShift+2*128,
        pB, pMB, pSum + 3*128, pSq + 3*128);
    finalize_k<<<1,128>>>(pSum+3*128, pSq+3*128, gl[3], bel[3], pScale+3*128, pShift+3*128, 64);

    // L4: 64 -> 128, d=1
    conv_block_k<64,128,32,1,true><<<dim3(16,16, NB*4), blk>>>(
        pB, pMB, Wl[4], bl[4], pScale+3*128, pShift+3*128,
        pA, pMA, pSum + 4*128, pSq + 4*128);
    finalize_k<<<1,128>>>(pSum+4*128, pSq+4*128, gl[4], bel[4], pScale+4*128, pShift+4*128, 128);

    // final 1x1 conv with L4 BN+leaky folded on load
    final_conv_k<<<NPIX/256, blk>>>(pA, pScale+4*128, pShift+4*128, Wf, bf, out);

    // mask output (after L4 maxpool) appended after x
    copy_mask_k<<<NPIX/256, blk>>>(pMA, out + (size_t)NB*64*HW);
}

// round 2
// speedup vs baseline: 1.1874x; 1.1874x over previous
#include <cuda_runtime.h>

#define NB   8
#define IMG  256
#define HW   (IMG*IMG)
#define NPIX (NB*HW)
#define BN_N 524288.0   /* 8*256*256 */

// ---------------- static scratch (no allocations allowed) ----------------
__device__ float  g_bufA[NB*128*HW];
__device__ float  g_bufB[NB*64*HW];
__device__ float  g_maskA[NPIX];
__device__ float  g_maskB[NPIX];
__device__ double g_sum[5*128];
__device__ double g_sq[5*128];
__device__ float  g_scale[5*128];
__device__ float  g_shift[5*128];

__global__ void zero_stats_k() {
    int i = blockIdx.x*256 + threadIdx.x;
    if (i < 5*128) { g_sum[i] = 0.0; g_sq[i] = 0.0; }
}

// ---------------- fused sparse-conv block --------------------------------
// Tile 32 wide x 16 tall; 256 threads; each thread computes 2 pixels
// (rows trow and trow+8) x CO_CHUNK output channels. Warp = one 32-px row
// => conflict-free xs loads; weight broadcast LDS.128 amortized over 2 px.
template<int CIN, int COUT, int CO_CHUNK, int D, bool ACT>
__global__ void __launch_bounds__(256) conv_block_k(
    const float* __restrict__ x,  const float* __restrict__ m_in,
    const float* __restrict__ W,  const float* __restrict__ bias,
    const float* __restrict__ scale, const float* __restrict__ shift,
    float* __restrict__ y, float* __restrict__ m_out,
    double* __restrict__ s_sum, double* __restrict__ s_sq)
{
    constexpr int TW_PIX = 32, TH_PIX = 16;
    constexpr int TW = TW_PIX + 2*D;
    constexpr int TH = TH_PIX + 2*D;
    constexpr int ET = TW*TH;
    constexpr int CI = 8;
    constexpr int CHUNKS = COUT / CO_CHUNK;

    __shared__ float xs[CI*ET];
    __shared__ float ms[ET];
    __shared__ __align__(16) float wsh[CI*9*CO_CHUNK];
    __shared__ float sred[CO_CHUNK][8];
    __shared__ float qred[CO_CHUNK][8];

    const int tid  = threadIdx.x;
    const int n    = blockIdx.z / CHUNKS;
    const int cc   = blockIdx.z % CHUNKS;
    const int co0  = cc * CO_CHUNK;
    const int y0   = blockIdx.y*TH_PIX - D;
    const int x0   = blockIdx.x*TW_PIX - D;
    const int tx   = tid & 31;
    const int trow = tid >> 5;          // 0..7, handles rows trow and trow+8

    // mask tile (zero-padded)
    for (int e = tid; e < ET; e += 256) {
        int iy = e / TW, ix = e % TW;
        int gy = y0 + iy, gx = x0 + ix;
        float mv = 0.f;
        if (gy >= 0 && gy < IMG && gx >= 0 && gx < IMG)
            mv = m_in[n*HW + gy*IMG + gx];
        ms[e] = mv;
    }

    float acc[2][CO_CHUNK];
#pragma unroll
    for (int p = 0; p < 2; ++p)
#pragma unroll
        for (int c = 0; c < CO_CHUNK; ++c) acc[p][c] = 0.f;

    for (int cb = 0; cb < CIN/CI; ++cb) {
        __syncthreads();   // covers ms availability (cb=0) and xs reuse
        // stage act(x)*mask for CI channels
        for (int e = tid; e < CI*ET; e += 256) {
            int ci = e / ET, r = e % ET;
            int iy = r / TW, ix = r % TW;
            int gy = y0 + iy, gx = x0 + ix;
            float v = 0.f;
            if (gy >= 0 && gy < IMG && gx >= 0 && gx < IMG) {
                float mv = ms[r];
                if (mv != 0.f) {
                    float raw = x[(size_t)(n*CIN + cb*CI + ci)*HW + gy*IMG + gx];
                    if (ACT) {
                        raw = scale[cb*CI + ci]*raw + shift[cb*CI + ci];
                        raw = raw >= 0.f ? raw : 0.01f*raw;
                    }
                    v = raw * mv;
                }
            }
            xs[e] = v;
        }
        // stage weights as [ci][tap][co]
        for (int e = tid; e < CI*9*CO_CHUNK; e += 256) {
            int co  = e % CO_CHUNK;
            int tap = (e / CO_CHUNK) % 9;
            int ci  = e / (9*CO_CHUNK);
            wsh[e] = W[(size_t)(co0 + co)*CIN*9 + (cb*CI + ci)*9 + tap];
        }
        __syncthreads();

#pragma unroll
        for (int ci = 0; ci < CI; ++ci) {
#pragma unroll
            for (int kh = 0; kh < 3; ++kh)
#pragma unroll
                for (int kw = 0; kw < 3; ++kw) {
                    const int tap = kh*3 + kw;
                    float xv0 = xs[ci*ET + (trow     + kh*D)*TW + tx + kw*D];
                    float xv1 = xs[ci*ET + (trow + 8 + kh*D)*TW + tx + kw*D];
                    const float4* wp = (const float4*)&wsh[(ci*9 + tap)*CO_CHUNK];
#pragma unroll
                    for (int c4 = 0; c4 < CO_CHUNK/4; ++c4) {
                        float4 w = wp[c4];
                        acc[0][c4*4+0] += xv0*w.x;  acc[1][c4*4+0] += xv1*w.x;
                        acc[0][c4*4+1] += xv0*w.y;  acc[1][c4*4+1] += xv1*w.y;
                        acc[0][c4*4+2] += xv0*w.z;  acc[1][c4*4+2] += xv1*w.z;
                        acc[0][c4*4+3] += xv0*w.w;  acc[1][c4*4+3] += xv1*w.w;
                    }
                }
        }
    }

    // epilogue: count normalization, mask maxpool, BN stats
    float inv[2];
    float vsum[CO_CHUNK], vsq[CO_CHUNK];
#pragma unroll
    for (int c = 0; c < CO_CHUNK; ++c) { vsum[c] = 0.f; vsq[c] = 0.f; }

#pragma unroll
    for (int p = 0; p < 2; ++p) {
        const int r = trow + p*8;
        float msum = 0.f, mmax = 0.f;
#pragma unroll
        for (int kh = 0; kh < 3; ++kh)
#pragma unroll
            for (int kw = 0; kw < 3; ++kw) {
                float mv = ms[(r + kh*D)*TW + tx + kw*D];
                msum += mv;
                mmax = fmaxf(mmax, mv);
            }
        inv[p] = 1.f / fmaxf((float)CIN * msum, 1e-5f);

        const int gy  = blockIdx.y*TH_PIX + r;
        const int gx  = blockIdx.x*TW_PIX + tx;
        const int pix = gy*IMG + gx;
        if (cc == 0) m_out[n*HW + pix] = mmax;

#pragma unroll
        for (int c = 0; c < CO_CHUNK; ++c) {
            float v = acc[p][c]*inv[p] + bias[co0 + c];
            y[(size_t)(n*COUT + co0 + c)*HW + pix] = v;
            vsum[c] += v;
            vsq[c]  += v*v;
        }
    }

    const int lane = tid & 31, w5 = tid >> 5;
#pragma unroll
    for (int c = 0; c < CO_CHUNK; ++c) {
        float s = vsum[c], q = vsq[c];
#pragma unroll
        for (int o = 16; o > 0; o >>= 1) {
            s += __shfl_xor_sync(0xffffffffu, s, o);
            q += __shfl_xor_sync(0xffffffffu, q, o);
        }
        if (lane == 0) { sred[c][w5] = s; qred[c][w5] = q; }
    }
    __syncthreads();
    if (tid < CO_CHUNK) {
        float s = 0.f, q = 0.f;
#pragma unroll
        for (int w = 0; w < 8; ++w) { s += sred[tid][w]; q += qred[tid][w]; }
        atomicAdd(&s_sum[co0 + tid], (double)s);
        atomicAdd(&s_sq [co0 + tid], (double)q);
    }
}

// ---------------- BN fold ------------------------------------------------
__global__ void finalize_k(const double* __restrict__ s_sum,
                           const double* __restrict__ s_sq,
                           const float* __restrict__ g,
                           const float* __restrict__ be,
                           float* __restrict__ scale,
                           float* __restrict__ shift, int C)
{
    int c = threadIdx.x;
    if (c < C) {
        double mean = s_sum[c] / BN_N;
        double var  = s_sq[c] / BN_N - mean*mean;
        float  sc   = g[c] * rsqrtf((float)(var + 1e-5));
        scale[c] = sc;
        shift[c] = be[c] - (float)mean * sc;
    }
}

// ---------------- final 1x1 conv (128 -> 64), 2 px/thread, 32-co chunks ---
__global__ void __launch_bounds__(256) final_conv_k(
    const float* __restrict__ x, const float* __restrict__ scale,
    const float* __restrict__ shift, const float* __restrict__ Wf,
    const float* __restrict__ bf, float* __restrict__ out)
{
    __shared__ __align__(16) float wsh[128*32];
    __shared__ float ssh[128], shh[128];
    const int tid = threadIdx.x;
    const int co0 = blockIdx.y * 32;
    for (int e = tid; e < 128*32; e += 256) {
        int ci = e >> 5, c = e & 31;
        wsh[e] = Wf[(co0 + c)*128 + ci];
    }
    if (tid < 128) { ssh[tid] = scale[tid]; shh[tid] = shift[tid]; }
    __syncthreads();

    int gid = blockIdx.x*256 + tid;          // 0 .. NPIX/2-1
    int n   = gid >> 15;
    int pix = (gid << 1) & (HW - 1);         // even pixel

    float acc[2][32];
#pragma unroll
    for (int p = 0; p < 2; ++p)
#pragma unroll
        for (int c = 0; c < 32; ++c) acc[p][c] = 0.f;

    for (int ci = 0; ci < 128; ++ci) {
        float2 v = *(const float2*)&x[((size_t)(n*128 + ci) << 16) + pix];
        float v0 = ssh[ci]*v.x + shh[ci]; v0 = v0 >= 0.f ? v0 : 0.01f*v0;
        float v1 = ssh[ci]*v.y + shh[ci]; v1 = v1 >= 0.f ? v1 : 0.01f*v1;
        const float4* wp = (const float4*)&wsh[ci*32];
#pragma unroll
        for (int c4 = 0; c4 < 8; ++c4) {
            float4 w = wp[c4];
            acc[0][c4*4+0] += v0*w.x;  acc[1][c4*4+0] += v1*w.x;
            acc[0][c4*4+1] += v0*w.y;  acc[1][c4*4+1] += v1*w.y;
            acc[0][c4*4+2] += v0*w.z;  acc[1][c4*4+2] += v1*w.z;
            acc[0][c4*4+3] += v0*w.w;  acc[1][c4*4+3] += v1*w.w;
        }
    }
#pragma unroll
    for (int c = 0; c < 32; ++c) {
        float2 o = make_float2(acc[0][c] + bf[co0 + c], acc[1][c] + bf[co0 + c]);
        *(float2*)&out[((size_t)(n*64 + co0 + c) << 16) + pix] = o;
    }
}

__global__ void copy_mask_k(const float* __restrict__ m, float* __restrict__ out) {
    int i = blockIdx.x*256 + threadIdx.x;
    if (i < NPIX) out[i] = m[i];
}

// ---------------- launcher ------------------------------------------------
extern "C" void kernel_launch(void* const* d_in, const int* in_sizes, int n_in,
                              void* d_out, int out_size)
{
    (void)in_sizes; (void)n_in; (void)out_size;
    const float* feat = (const float*)d_in[0];
    const float* mask = (const float*)d_in[1];
    const float* Wl[5]; const float* bl[5]; const float* gl[5]; const float* bel[5];
    for (int l = 0; l < 5; ++l) {
        Wl[l]  = (const float*)d_in[2 + 4*l];
        bl[l]  = (const float*)d_in[3 + 4*l];
        gl[l]  = (const float*)d_in[4 + 4*l];
        bel[l] = (const float*)d_in[5 + 4*l];
    }
    const float* Wf = (const float*)d_in[22];
    const float* bf = (const float*)d_in[23];
    float* out = (float*)d_out;

    float *pA, *pB, *pMA, *pMB, *pScale, *pShift;
    double *pSum, *pSq;
    cudaGetSymbolAddress((void**)&pA,     g_bufA);
    cudaGetSymbolAddress((void**)&pB,     g_bufB);
    cudaGetSymbolAddress((void**)&pMA,    g_maskA);
    cudaGetSymbolAddress((void**)&pMB,    g_maskB);
    cudaGetSymbolAddress((void**)&pSum,   g_sum);
    cudaGetSymbolAddress((void**)&pSq,    g_sq);
    cudaGetSymbolAddress((void**)&pScale, g_scale);
    cudaGetSymbolAddress((void**)&pShift, g_shift);

    zero_stats_k<<<3, 256>>>();

    dim3 blk(256);
    dim3 tiles(IMG/32, IMG/16);   // 8 x 16 tiles

    // L0: 32 -> 16, d=1
    conv_block_k<32,16,16,1,false><<<dim3(tiles.x,tiles.y, NB*1), blk>>>(
        feat, mask, Wl[0], bl[0], nullptr, nullptr,
        pA, pMA, pSum + 0*128, pSq + 0*128);
    finalize_k<<<1,128>>>(pSum+0*128, pSq+0*128, gl[0], bel[0], pScale+0*128, pShift+0*128, 16);

    // L1: 16 -> 32, d=2
    conv_block_k<16,32,32,2,true><<<dim3(tiles.x,tiles.y, NB*1), blk>>>(
        pA, pMA, Wl[1], bl[1], pScale+0*128, pShift+0*128,
        pB, pMB, pSum + 1*128, pSq + 1*128);
    finalize_k<<<1,128>>>(pSum+1*128, pSq+1*128, gl[1], bel[1], pScale+1*128, pShift+1*128, 32);

    // L2: 32 -> 64, d=1
    conv_block_k<32,64,32,1,true><<<dim3(tiles.x,tiles.y, NB*2), blk>>>(
        pB, pMB, Wl[2], bl[2], pScale+1*128, pShift+1*128,
        pA, pMA, pSum + 2*128, pSq + 2*128);
    finalize_k<<<1,128>>>(pSum+2*128, pSq+2*128, gl[2], bel[2], pScale+2*128, pShift+2*128, 64);

    // L3: 64 -> 64, d=2
    conv_block_k<64,64,32,2,true><<<dim3(tiles.x,tiles.y, NB*2), blk>>>(
        pA, pMA, Wl[3], bl[3], pScale+2*128, pShift+2*128,
        pB, pMB, pSum + 3*128, pSq + 3*128);
    finalize_k<<<1,128>>>(pSum+3*128, pSq+3*128, gl[3], bel[3], pScale+3*128, pShift+3*128, 64);

    // L4: 64 -> 128, d=1
    conv_block_k<64,128,32,1,true><<<dim3(tiles.x,tiles.y, NB*4), blk>>>(
        pB, pMB, Wl[4], bl[4], pScale+3*128, pShift+3*128,
        pA, pMA, pSum + 4*128, pSq + 4*128);
    finalize_k<<<1,128>>>(pSum+4*128, pSq+4*128, gl[4], bel[4], pScale+4*128, pShift+4*128, 128);

    // final 1x1 conv with L4 BN+leaky folded on load
    final_conv_k<<<dim3(NPIX/512, 2), blk>>>(pA, pScale+4*128, pShift+4*128, Wf, bf, out);

    // mask output appended after x
    copy_mask_k<<<NPIX/256, blk>>>(pMA, out + (size_t)NB*64*HW);
}